// round 7
// baseline (speedup 1.0000x reference)
#include <cuda_runtime.h>
#include <cstdint>
#include <math.h>

// Problem constants (fixed shapes)
#define T    2048
#define DM   1024
#define NE   8
#define FF   4096

#define KC   16            // K floats per chunk
#define PAD  20            // smem row stride in floats (16 + 4)

// ---------------- scratch (static device globals; no allocation) ----------------
__device__ int   g_count[NE];
__device__ int   g_cursor[NE];
__device__ int   g_offset[NE];
__device__ int   g_topk_idx[T * 2];
__device__ float g_topk_w[T * 2];
__device__ int   g_tok[2 * T];
__device__ float g_wgt[2 * T];
__device__ float g_inter[(size_t)(2 * T) * FF];   // 64 MB fp32 scratch

#define DEVINL __device__ __forceinline__

DEVINL uint32_t to_tf32(float f) {
    uint32_t r;
    asm("cvt.rna.tf32.f32 %0, %1;" : "=r"(r) : "f"(f));
    return r;
}
DEVINL uint4 to_tf32_v4(float4 v) {
    return make_uint4(to_tf32(v.x), to_tf32(v.y), to_tf32(v.z), to_tf32(v.w));
}

DEVINL void mma_tf32(float* d, const uint32_t* a, const uint32_t* b) {
    asm volatile(
        "mma.sync.aligned.m16n8k8.row.col.f32.tf32.tf32.f32 "
        "{%0,%1,%2,%3}, {%4,%5,%6,%7}, {%8,%9}, {%0,%1,%2,%3};"
        : "+f"(d[0]), "+f"(d[1]), "+f"(d[2]), "+f"(d[3])
        : "r"(a[0]), "r"(a[1]), "r"(a[2]), "r"(a[3]), "r"(b[0]), "r"(b[1]));
}

// ---------------- init ----------------
__global__ void init_kernel() {
    int i = threadIdx.x;
    if (i < NE) { g_count[i] = 0; g_cursor[i] = 0; }
}

// ---------------- router ----------------
__global__ void router_kernel(const float* __restrict__ x,
                              const float* __restrict__ gw,
                              float* __restrict__ logits_out) {
    int t = blockIdx.x;
    int warp = threadIdx.x >> 5;
    int lane = threadIdx.x & 31;
    const float* xr = x + (size_t)t * DM;
    const float* gr = gw + (size_t)warp * DM;
    float s = 0.f;
    for (int j = lane; j < DM; j += 32) s += xr[j] * gr[j];
    #pragma unroll
    for (int o = 16; o > 0; o >>= 1) s += __shfl_xor_sync(0xFFFFFFFFu, s, o);

    __shared__ float lg[NE];
    if (lane == 0) lg[warp] = s;
    __syncthreads();

    if (threadIdx.x == 0) {
        float mx = lg[0];
        #pragma unroll
        for (int e = 1; e < NE; e++) mx = fmaxf(mx, lg[e]);
        float p[NE];
        #pragma unroll
        for (int e = 0; e < NE; e++) p[e] = expf(lg[e] - mx);
        int i0 = 0;
        #pragma unroll
        for (int e = 1; e < NE; e++) if (p[e] > p[i0]) i0 = e;
        int i1 = -1;
        #pragma unroll
        for (int e = 0; e < NE; e++) {
            if (e == i0) continue;
            if (i1 < 0 || p[e] > p[i1]) i1 = e;
        }
        float inv = 1.f / (p[i0] + p[i1]);
        g_topk_idx[t * 2 + 0] = i0;
        g_topk_idx[t * 2 + 1] = i1;
        g_topk_w[t * 2 + 0] = p[i0] * inv;
        g_topk_w[t * 2 + 1] = p[i1] * inv;
        atomicAdd(&g_count[i0], 1);
        atomicAdd(&g_count[i1], 1);
        #pragma unroll
        for (int e = 0; e < NE; e++) logits_out[(size_t)t * NE + e] = lg[e];
    }
}

// ---------------- offsets + assignment (single block) ----------------
__global__ void assign_kernel() {
    if (threadIdx.x == 0) {
        int o = 0;
        #pragma unroll
        for (int e = 0; e < NE; e++) { g_offset[e] = o; o += g_count[e]; }
    }
    __syncthreads();
    for (int t = threadIdx.x; t < T; t += blockDim.x) {
        #pragma unroll
        for (int k = 0; k < 2; k++) {
            int e = g_topk_idx[t * 2 + k];
            int pos = atomicAdd(&g_cursor[e], 1);
            int g = g_offset[e] + pos;
            g_tok[g] = t;
            g_wgt[g] = g_topk_w[t * 2 + k];
        }
    }
}

// smem sizing (uint32 units)
#define TILE128_U32 (128 * PAD)                       // 2560
#define TILE64_U32  (64 * PAD)                        // 1280
#define G1_SMEM_U32 (128 + 2 * (TILE128_U32 + 2 * TILE64_U32))  // toks + 2 stages x {A128,B1_64,B3_64}
#define G2_SMEM_U32 (256 + 2 * 2 * TILE128_U32)                 // toks+wgts + 2 stages x {A128,B128}
#define G1_SMEM_BYTES (G1_SMEM_U32 * 4)
#define G2_SMEM_BYTES (G2_SMEM_U32 * 4)

// ================= GEMM1 (tf32 mma.sync): inter = silu(X w1^T) * (X w3^T) =================
// 256 threads, 2 CTAs/SM. Block 128x64, warps 4(M)x2(N), warp tile 32x32, KC=16.
__global__ __launch_bounds__(256, 2)
void gemm1_tc(const float* __restrict__ x,
              const float* __restrict__ w1,
              const float* __restrict__ w3) {
    int e = blockIdx.z;
    int cnt = g_count[e];
    int m0 = blockIdx.y * 128;
    if (m0 >= cnt) return;
    int n0 = blockIdx.x * 64;
    int base = g_offset[e];

    extern __shared__ uint32_t sm[];
    int* toks = (int*)sm;
    uint32_t* Abuf  = sm + 128;                              // 2 x TILE128
    uint32_t* B1buf = sm + 128 + 2 * TILE128_U32;            // 2 x TILE64
    uint32_t* B3buf = sm + 128 + 2 * TILE128_U32 + 2 * TILE64_U32;

    int tid = threadIdx.x;
    int wid = tid >> 5, lane = tid & 31;
    int g = lane >> 2, tq = lane & 3;
    int warpM = wid >> 1, warpN = wid & 1;   // 4(M) x 2(N)

    if (tid < 128) {
        int m = m0 + tid;
        toks[tid] = (m < cnt) ? g_tok[base + m] : -1;
    }
    __syncthreads();

    const float* W1 = w1 + (size_t)e * FF * DM + (size_t)n0 * DM;
    const float* W3 = w3 + (size_t)e * FF * DM + (size_t)n0 * DM;

    float acc1[2][4][4], acc3[2][4][4];
    #pragma unroll
    for (int i = 0; i < 2; i++)
        #pragma unroll
        for (int j = 0; j < 4; j++)
            #pragma unroll
            for (int c = 0; c < 4; c++) { acc1[i][j][c] = 0.f; acc3[i][j][c] = 0.f; }

    // per chunk: A = 128x16 = 512 f4 (2/thr), B1 = B3 = 64x16 = 256 f4 (1/thr)
    float4 ra[2], rb1, rb3;

    auto ldg_chunk = [&](int k0) {
        #pragma unroll
        for (int p = 0; p < 2; p++) {
            int f = tid + p * 256;
            int row = f >> 2, j = f & 3;     // 4 f4 per row
            int tk = toks[row];
            ra[p] = make_float4(0.f, 0.f, 0.f, 0.f);
            if (tk >= 0) ra[p] = *(const float4*)(x + (size_t)tk * DM + k0 + j * 4);
        }
        {
            int row = tid >> 2, j = tid & 3;
            rb1 = *(const float4*)(W1 + (size_t)row * DM + k0 + j * 4);
            rb3 = *(const float4*)(W3 + (size_t)row * DM + k0 + j * 4);
        }
    };
    auto sts_chunk = [&](int buf) {
        uint32_t* A  = Abuf  + buf * TILE128_U32;
        uint32_t* B1 = B1buf + buf * TILE64_U32;
        uint32_t* B3 = B3buf + buf * TILE64_U32;
        #pragma unroll
        for (int p = 0; p < 2; p++) {
            int f = tid + p * 256;
            int row = f >> 2, j = f & 3;
            *(uint4*)(A + row * PAD + j * 4) = to_tf32_v4(ra[p]);
        }
        {
            int row = tid >> 2, j = tid & 3;
            *(uint4*)(B1 + row * PAD + j * 4) = to_tf32_v4(rb1);
            *(uint4*)(B3 + row * PAD + j * 4) = to_tf32_v4(rb3);
        }
    };
    auto compute_chunk = [&](int buf) {
        const uint32_t* A  = Abuf  + buf * TILE128_U32;
        const uint32_t* B1 = B1buf + buf * TILE64_U32;
        const uint32_t* B3 = B3buf + buf * TILE64_U32;
        #pragma unroll
        for (int ks = 0; ks < 2; ks++) {
            int kk = ks * 8 + tq;
            uint32_t afr[2][4];
            #pragma unroll
            for (int mt = 0; mt < 2; mt++) {
                int m = warpM * 32 + mt * 16 + g;
                afr[mt][0] = A[m * PAD + kk];
                afr[mt][1] = A[(m + 8) * PAD + kk];
                afr[mt][2] = A[m * PAD + kk + 4];
                afr[mt][3] = A[(m + 8) * PAD + kk + 4];
            }
            #pragma unroll
            for (int nt = 0; nt < 4; nt++) {
                int n = warpN * 32 + nt * 8 + g;
                uint32_t b1f[2] = { B1[n * PAD + kk], B1[n * PAD + kk + 4] };
                uint32_t b3f[2] = { B3[n * PAD + kk], B3[n * PAD + kk + 4] };
                #pragma unroll
                for (int mt = 0; mt < 2; mt++) {
                    mma_tf32(acc1[mt][nt], afr[mt], b1f);
                    mma_tf32(acc3[mt][nt], afr[mt], b3f);
                }
            }
        }
    };

    const int NIT = DM / KC;   // 64
    ldg_chunk(0);
    sts_chunk(0);
    __syncthreads();
    for (int it = 0; it < NIT; ++it) {
        if (it + 1 < NIT) ldg_chunk((it + 1) * KC);
        compute_chunk(it & 1);
        if (it + 1 < NIT) sts_chunk((it + 1) & 1);
        __syncthreads();
    }

    // epilogue: silu(up) * gate -> g_inter (valid rows only)
    #pragma unroll
    for (int mt = 0; mt < 2; mt++) {
        #pragma unroll
        for (int half = 0; half < 2; half++) {
            int rl = warpM * 32 + mt * 16 + half * 8 + g;
            int m = m0 + rl;
            if (m < cnt) {
                float* orow = g_inter + (size_t)(base + m) * FF + n0;
                #pragma unroll
                for (int nt = 0; nt < 4; nt++) {
                    int col = warpN * 32 + nt * 8 + 2 * tq;
                    float u0 = acc1[mt][nt][half * 2 + 0];
                    float u1 = acc1[mt][nt][half * 2 + 1];
                    float g0 = acc3[mt][nt][half * 2 + 0];
                    float g1 = acc3[mt][nt][half * 2 + 1];
                    float2 o;
                    o.x = u0 / (1.f + __expf(-u0)) * g0;
                    o.y = u1 / (1.f + __expf(-u1)) * g1;
                    *(float2*)(orow + col) = o;
                }
            }
        }
    }
}

// ================= GEMM2 (tf32 mma.sync): out += cw * (inter w2^T) =================
// 256 threads, 2 CTAs/SM. Block 128x128, warps 2(M)x4(N), warp tile 64x32, KC=16.
__global__ __launch_bounds__(256, 2)
void gemm2_tc(const float* __restrict__ w2, float* __restrict__ out) {
    int e = blockIdx.z;
    int cnt = g_count[e];
    int m0 = blockIdx.y * 128;
    if (m0 >= cnt) return;
    int n0 = blockIdx.x * 128;
    int base = g_offset[e];

    extern __shared__ uint32_t sm[];
    int*   toks = (int*)sm;                 // [128]
    float* wgts = (float*)(sm + 128);       // [128]
    uint32_t* Abuf = sm + 256;                         // 2 x TILE128
    uint32_t* Bbuf = sm + 256 + 2 * TILE128_U32;       // 2 x TILE128

    int tid = threadIdx.x;
    int wid = tid >> 5, lane = tid & 31;
    int g = lane >> 2, tq = lane & 3;
    int warpM = wid >> 2, warpN = wid & 3;   // 2(M) x 4(N)

    if (tid < 128) {
        int m = m0 + tid;
        bool v = (m < cnt);
        toks[tid] = v ? g_tok[base + m] : -1;
        wgts[tid] = v ? g_wgt[base + m] : 0.f;
    }
    __syncthreads();

    const float* W2 = w2 + (size_t)e * DM * FF + (size_t)n0 * FF;
    const float* Ain = g_inter + (size_t)(base + m0) * FF;
    int mlim = cnt - m0;

    float acc[4][4][4];
    #pragma unroll
    for (int i = 0; i < 4; i++)
        #pragma unroll
        for (int j = 0; j < 4; j++)
            #pragma unroll
            for (int c = 0; c < 4; c++) acc[i][j][c] = 0.f;

    // per chunk: A = 128x16 = 512 f4 (2/thr), B = 128x16 = 512 f4 (2/thr)
    float4 ra[2], rb[2];
    auto ldg_chunk = [&](int k0) {
        #pragma unroll
        for (int p = 0; p < 2; p++) {
            int f = tid + p * 256;
            int row = f >> 2, j = f & 3;
            ra[p] = make_float4(0.f, 0.f, 0.f, 0.f);
            if (row < mlim) ra[p] = *(const float4*)(Ain + (size_t)row * FF + k0 + j * 4);
            rb[p] = *(const float4*)(W2 + (size_t)row * FF + k0 + j * 4);
        }
    };
    auto sts_chunk = [&](int buf) {
        uint32_t* A = Abuf + buf * TILE128_U32;
        uint32_t* B = Bbuf + buf * TILE128_U32;
        #pragma unroll
        for (int p = 0; p < 2; p++) {
            int f = tid + p * 256;
            int row = f >> 2, j = f & 3;
            *(uint4*)(A + row * PAD + j * 4) = to_tf32_v4(ra[p]);
            *(uint4*)(B + row * PAD + j * 4) = to_tf32_v4(rb[p]);
        }
    };
    auto compute_chunk = [&](int buf) {
        const uint32_t* A = Abuf + buf * TILE128_U32;
        const uint32_t* B = Bbuf + buf * TILE128_U32;
        #pragma unroll
        for (int ks = 0; ks < 2; ks++) {
            int kk = ks * 8 + tq;
            uint32_t afr[4][4];
            #pragma unroll
            for (int mt = 0; mt < 4; mt++) {
                int m = warpM * 64 + mt * 16 + g;
                afr[mt][0] = A[m * PAD + kk];
                afr[mt][1] = A[(m + 8) * PAD + kk];
                afr[mt][2] = A[m * PAD + kk + 4];
                afr[mt][3] = A[(m + 8) * PAD + kk + 4];
            }
            #pragma unroll
            for (int nt = 0; nt < 4; nt++) {
                int n = warpN * 32 + nt * 8 + g;
                uint32_t bf[2] = { B[n * PAD + kk], B[n * PAD + kk + 4] };
                #pragma unroll
                for (int mt = 0; mt < 4; mt++) mma_tf32(acc[mt][nt], afr[mt], bf);
            }
        }
    };

    const int NIT = FF / KC;   // 256
    ldg_chunk(0);
    sts_chunk(0);
    __syncthreads();
    for (int it = 0; it < NIT; ++it) {
        if (it + 1 < NIT) ldg_chunk((it + 1) * KC);
        compute_chunk(it & 1);
        if (it + 1 < NIT) sts_chunk((it + 1) & 1);
        __syncthreads();
    }

    // epilogue: weighted deterministic scatter-add (2 contributions per element)
    #pragma unroll
    for (int mt = 0; mt < 4; mt++) {
        #pragma unroll
        for (int half = 0; half < 2; half++) {
            int rl = warpM * 64 + mt * 16 + half * 8 + g;
            int t = toks[rl];
            if (t >= 0) {
                float w = wgts[rl];
                float* orow = out + (size_t)t * DM + n0;
                #pragma unroll
                for (int nt = 0; nt < 4; nt++) {
                    int col = warpN * 32 + nt * 8 + 2 * tq;
                    atomicAdd(orow + col,     w * acc[mt][nt][half * 2 + 0]);
                    atomicAdd(orow + col + 1, w * acc[mt][nt][half * 2 + 1]);
                }
            }
        }
    }
}

// ---------------- launch ----------------
extern "C" void kernel_launch(void* const* d_in, const int* in_sizes, int n_in,
                              void* d_out, int out_size) {
    const float* x  = (const float*)d_in[0];   // [T, DM]
    const float* gw = (const float*)d_in[1];   // [NE, DM]
    const float* w1 = (const float*)d_in[2];   // [NE, FF, DM]
    const float* w3 = (const float*)d_in[3];   // [NE, FF, DM]
    const float* w2 = (const float*)d_in[4];   // [NE, DM, FF]

    float* out    = (float*)d_out;             // [T, DM] then router_logits [T, NE]
    float* logits = out + (size_t)T * DM;

    cudaFuncSetAttribute(gemm1_tc, cudaFuncAttributeMaxDynamicSharedMemorySize, G1_SMEM_BYTES);
    cudaFuncSetAttribute(gemm2_tc, cudaFuncAttributeMaxDynamicSharedMemorySize, G2_SMEM_BYTES);

    cudaMemsetAsync(d_out, 0, (size_t)T * DM * sizeof(float));
    init_kernel<<<1, 32>>>();
    router_kernel<<<T, 256>>>(x, gw, logits);
    assign_kernel<<<1, 256>>>();
    gemm1_tc<<<dim3(FF / 64, (2 * T) / 128, NE), 256, G1_SMEM_BYTES>>>(x, w1, w3);
    gemm2_tc<<<dim3(DM / 128, (2 * T) / 128, NE), 256, G2_SMEM_BYTES>>>(w2, out);
}

// round 8
// speedup vs baseline: 1.2818x; 1.2818x over previous
#include <cuda_runtime.h>
#include <cstdint>
#include <math.h>

// Problem constants (fixed shapes)
#define T    2048
#define DM   1024
#define NE   8
#define FF   4096

#define KC   32            // K floats per chunk
#define PAD  36            // smem row stride in floats (32 + 4)

// ---------------- scratch (static device globals; no allocation) ----------------
__device__ int   g_count[NE];
__device__ int   g_cursor[NE];
__device__ int   g_offset[NE];
__device__ int   g_topk_idx[T * 2];
__device__ float g_topk_w[T * 2];
__device__ int   g_tok[2 * T];
__device__ float g_wgt[2 * T];
__device__ float g_inter[(size_t)(2 * T) * FF];   // 64 MB fp32 scratch

#define DEVINL __device__ __forceinline__

DEVINL uint32_t smem_u32(const void* p) {
    uint32_t a;
    asm("{ .reg .u64 t; cvta.to.shared.u64 t, %1; cvt.u32.u64 %0, t; }" : "=r"(a) : "l"(p));
    return a;
}

DEVINL uint32_t to_tf32(float f) {
    uint32_t r;
    asm("cvt.rna.tf32.f32 %0, %1;" : "=r"(r) : "f"(f));
    return r;
}
DEVINL uint4 to_tf32_v4(float4 v) {
    return make_uint4(to_tf32(v.x), to_tf32(v.y), to_tf32(v.z), to_tf32(v.w));
}

DEVINL void mma_tf32(float* d, const uint32_t* a, const uint32_t* b) {
    asm volatile(
        "mma.sync.aligned.m16n8k8.row.col.f32.tf32.tf32.f32 "
        "{%0,%1,%2,%3}, {%4,%5,%6,%7}, {%8,%9}, {%0,%1,%2,%3};"
        : "+f"(d[0]), "+f"(d[1]), "+f"(d[2]), "+f"(d[3])
        : "r"(a[0]), "r"(a[1]), "r"(a[2]), "r"(a[3]), "r"(b[0]), "r"(b[1]));
}

// ldmatrix x4: four 8x8 b16 tiles == four 8x4 fp32 tiles; per-thread result
// mapping (thread r*4+c <- elem (r,c)) matches the tf32 mma fragment layout.
DEVINL void ldsm_x4(uint32_t addr, uint32_t* r) {
    asm volatile("ldmatrix.sync.aligned.m8n8.x4.shared.b16 {%0,%1,%2,%3}, [%4];"
        : "=r"(r[0]), "=r"(r[1]), "=r"(r[2]), "=r"(r[3]) : "r"(addr));
}

// ---------------- init ----------------
__global__ void init_kernel() {
    int i = threadIdx.x;
    if (i < NE) { g_count[i] = 0; g_cursor[i] = 0; }
}

// ---------------- router ----------------
__global__ void router_kernel(const float* __restrict__ x,
                              const float* __restrict__ gw,
                              float* __restrict__ logits_out) {
    int t = blockIdx.x;
    int warp = threadIdx.x >> 5;
    int lane = threadIdx.x & 31;
    const float* xr = x + (size_t)t * DM;
    const float* gr = gw + (size_t)warp * DM;
    float s = 0.f;
    for (int j = lane; j < DM; j += 32) s += xr[j] * gr[j];
    #pragma unroll
    for (int o = 16; o > 0; o >>= 1) s += __shfl_xor_sync(0xFFFFFFFFu, s, o);

    __shared__ float lg[NE];
    if (lane == 0) lg[warp] = s;
    __syncthreads();

    if (threadIdx.x == 0) {
        float mx = lg[0];
        #pragma unroll
        for (int e = 1; e < NE; e++) mx = fmaxf(mx, lg[e]);
        float p[NE];
        #pragma unroll
        for (int e = 0; e < NE; e++) p[e] = expf(lg[e] - mx);
        int i0 = 0;
        #pragma unroll
        for (int e = 1; e < NE; e++) if (p[e] > p[i0]) i0 = e;
        int i1 = -1;
        #pragma unroll
        for (int e = 0; e < NE; e++) {
            if (e == i0) continue;
            if (i1 < 0 || p[e] > p[i1]) i1 = e;
        }
        float inv = 1.f / (p[i0] + p[i1]);
        g_topk_idx[t * 2 + 0] = i0;
        g_topk_idx[t * 2 + 1] = i1;
        g_topk_w[t * 2 + 0] = p[i0] * inv;
        g_topk_w[t * 2 + 1] = p[i1] * inv;
        atomicAdd(&g_count[i0], 1);
        atomicAdd(&g_count[i1], 1);
        #pragma unroll
        for (int e = 0; e < NE; e++) logits_out[(size_t)t * NE + e] = lg[e];
    }
}

// ---------------- offsets + assignment (single block) ----------------
__global__ void assign_kernel() {
    if (threadIdx.x == 0) {
        int o = 0;
        #pragma unroll
        for (int e = 0; e < NE; e++) { g_offset[e] = o; o += g_count[e]; }
    }
    __syncthreads();
    for (int t = threadIdx.x; t < T; t += blockDim.x) {
        #pragma unroll
        for (int k = 0; k < 2; k++) {
            int e = g_topk_idx[t * 2 + k];
            int pos = atomicAdd(&g_cursor[e], 1);
            int g = g_offset[e] + pos;
            g_tok[g] = t;
            g_wgt[g] = g_topk_w[t * 2 + k];
        }
    }
}

// smem sizing (uint32 units)
#define TILE128_U32 (128 * PAD)                      // 4608
#define TILE256_U32 (256 * PAD)                      // 9216
#define G1_SMEM_U32 (128 + 2 * 3 * TILE128_U32)      // toks + 2 stages x {A,B1,B3}
#define G2_SMEM_U32 (512 + 2 * (TILE256_U32 + TILE128_U32)) // toks+wgts + 2 stages x {A256,B128}
#define G1_SMEM_BYTES (G1_SMEM_U32 * 4)
#define G2_SMEM_BYTES (G2_SMEM_U32 * 4)

// ================= GEMM1 (tf32 mma.sync + ldmatrix): inter = silu(X w1^T) * (X w3^T) =====
// 512 threads, block 128x128, warp tile 32x32 (mt=2, nt=4), 16 warps.
__global__ __launch_bounds__(512, 1)
void gemm1_tc(const float* __restrict__ x,
              const float* __restrict__ w1,
              const float* __restrict__ w3) {
    int e = blockIdx.z;
    int cnt = g_count[e];
    int m0 = blockIdx.y * 128;
    if (m0 >= cnt) return;
    int n0 = blockIdx.x * 128;
    int base = g_offset[e];

    extern __shared__ uint32_t sm[];
    int* toks = (int*)sm;
    uint32_t* Abuf  = sm + 128;
    uint32_t* B1buf = sm + 128 + 2 * TILE128_U32;
    uint32_t* B3buf = sm + 128 + 4 * TILE128_U32;

    uint32_t sbA  = smem_u32(Abuf);
    uint32_t sbB1 = smem_u32(B1buf);
    uint32_t sbB3 = smem_u32(B3buf);

    int tid = threadIdx.x;
    int wid = tid >> 5, lane = tid & 31;
    int g = lane >> 2, tq = lane & 3;
    int grp = lane >> 3, rowi = lane & 7;     // ldmatrix groups
    int warpM = wid >> 2, warpN = wid & 3;    // 4x4 warps

    if (tid < 128) {
        int m = m0 + tid;
        toks[tid] = (m < cnt) ? g_tok[base + m] : -1;
    }
    __syncthreads();

    const float* W1 = w1 + (size_t)e * FF * DM + (size_t)n0 * DM;
    const float* W3 = w3 + (size_t)e * FF * DM + (size_t)n0 * DM;

    float acc1[2][4][4], acc3[2][4][4];
    #pragma unroll
    for (int i = 0; i < 2; i++)
        #pragma unroll
        for (int j = 0; j < 4; j++)
            #pragma unroll
            for (int c = 0; c < 4; c++) { acc1[i][j][c] = 0.f; acc3[i][j][c] = 0.f; }

    // producers: 1024 float4 per tile, 512 threads -> 2 per thread
    float4 ra[2], rb1[2], rb3[2];

    auto ldg_chunk = [&](int k0) {
        #pragma unroll
        for (int p = 0; p < 2; p++) {
            int f = tid + p * 512;
            int row = f >> 3, j = f & 7;
            int tk = toks[row];
            ra[p] = make_float4(0.f, 0.f, 0.f, 0.f);
            if (tk >= 0) ra[p] = *(const float4*)(x + (size_t)tk * DM + k0 + j * 4);
            rb1[p] = *(const float4*)(W1 + (size_t)row * DM + k0 + j * 4);
            rb3[p] = *(const float4*)(W3 + (size_t)row * DM + k0 + j * 4);
        }
    };
    auto sts_chunk = [&](int buf) {
        uint32_t* A  = Abuf  + buf * TILE128_U32;
        uint32_t* B1 = B1buf + buf * TILE128_U32;
        uint32_t* B3 = B3buf + buf * TILE128_U32;
        #pragma unroll
        for (int p = 0; p < 2; p++) {
            int f = tid + p * 512;
            int row = f >> 3, j = f & 7;
            uint32_t off = row * PAD + j * 4;
            *(uint4*)(A + off)  = to_tf32_v4(ra[p]);
            *(uint4*)(B1 + off) = to_tf32_v4(rb1[p]);
            *(uint4*)(B3 + off) = to_tf32_v4(rb3[p]);
        }
    };
    auto compute_chunk = [&](int buf) {
        uint32_t Ab  = sbA  + buf * TILE128_U32 * 4;
        uint32_t B1b = sbB1 + buf * TILE128_U32 * 4;
        uint32_t B3b = sbB3 + buf * TILE128_U32 * 4;
        #pragma unroll
        for (int ks = 0; ks < 4; ks++) {
            // A frags: matrices (m-lo,k-lo),(m-hi,k-lo),(m-lo,k-hi),(m-hi,k-hi)
            uint32_t afr[2][4];
            #pragma unroll
            for (int mt = 0; mt < 2; mt++) {
                int arow = warpM * 32 + mt * 16 + (grp & 1) * 8 + rowi;
                uint32_t addr = Ab + (uint32_t)(arow * PAD + ks * 8 + (grp >> 1) * 4) * 4;
                ldsm_x4(addr, afr[mt]);
            }
            // B frags: per nt-pair, matrices (n-lo,k-lo),(n-lo,k-hi),(n-hi,k-lo),(n-hi,k-hi)
            uint32_t b1f[2][4], b3f[2][4];
            #pragma unroll
            for (int np = 0; np < 2; np++) {
                int nrow = warpN * 32 + np * 16 + (grp >> 1) * 8 + rowi;
                uint32_t off = (uint32_t)(nrow * PAD + ks * 8 + (grp & 1) * 4) * 4;
                ldsm_x4(B1b + off, b1f[np]);
                ldsm_x4(B3b + off, b3f[np]);
            }
            #pragma unroll
            for (int np = 0; np < 2; np++) {
                #pragma unroll
                for (int sub = 0; sub < 2; sub++) {
                    int nt = np * 2 + sub;
                    #pragma unroll
                    for (int mt = 0; mt < 2; mt++) {
                        mma_tf32(acc1[mt][nt], afr[mt], &b1f[np][sub * 2]);
                        mma_tf32(acc3[mt][nt], afr[mt], &b3f[np][sub * 2]);
                    }
                }
            }
        }
    };

    const int NIT = DM / KC;   // 32
    ldg_chunk(0);
    sts_chunk(0);
    __syncthreads();
    for (int it = 0; it < NIT; ++it) {
        if (it + 1 < NIT) ldg_chunk((it + 1) * KC);
        compute_chunk(it & 1);
        if (it + 1 < NIT) sts_chunk((it + 1) & 1);
        __syncthreads();
    }

    // epilogue: silu(up) * gate -> g_inter (valid rows only)
    #pragma unroll
    for (int mt = 0; mt < 2; mt++) {
        #pragma unroll
        for (int half = 0; half < 2; half++) {
            int rl = warpM * 32 + mt * 16 + half * 8 + g;
            int m = m0 + rl;
            if (m < cnt) {
                float* orow = g_inter + (size_t)(base + m) * FF + n0;
                #pragma unroll
                for (int nt = 0; nt < 4; nt++) {
                    int col = warpN * 32 + nt * 8 + 2 * tq;
                    float u0 = acc1[mt][nt][half * 2 + 0];
                    float u1 = acc1[mt][nt][half * 2 + 1];
                    float g0 = acc3[mt][nt][half * 2 + 0];
                    float g1 = acc3[mt][nt][half * 2 + 1];
                    float2 o;
                    o.x = u0 / (1.f + __expf(-u0)) * g0;
                    o.y = u1 / (1.f + __expf(-u1)) * g1;
                    *(float2*)(orow + col) = o;
                }
            }
        }
    }
}

// ================= GEMM2 (tf32 mma.sync + ldmatrix): out += cw * (inter w2^T) =============
// 512 threads, block 256x128, warp tile 64x32 (mt=4, nt=4), 16 warps.
__global__ __launch_bounds__(512, 1)
void gemm2_tc(const float* __restrict__ w2, float* __restrict__ out) {
    int e = blockIdx.z;
    int cnt = g_count[e];
    int m0 = blockIdx.y * 256;
    if (m0 >= cnt) return;
    int n0 = blockIdx.x * 128;
    int base = g_offset[e];

    extern __shared__ uint32_t sm[];
    int*   toks = (int*)sm;                 // [256]
    float* wgts = (float*)(sm + 256);       // [256]
    uint32_t* Abuf = sm + 512;                            // 2 x TILE256
    uint32_t* Bbuf = sm + 512 + 2 * TILE256_U32;          // 2 x TILE128

    uint32_t sbA = smem_u32(Abuf);
    uint32_t sbB = smem_u32(Bbuf);

    int tid = threadIdx.x;
    int wid = tid >> 5, lane = tid & 31;
    int g = lane >> 2, tq = lane & 3;
    int grp = lane >> 3, rowi = lane & 7;
    int warpM = wid >> 2, warpN = wid & 3;   // 4(M) x 4(N) warps

    if (tid < 256) {
        int m = m0 + tid;
        bool v = (m < cnt);
        toks[tid] = v ? g_tok[base + m] : -1;
        wgts[tid] = v ? g_wgt[base + m] : 0.f;
    }
    __syncthreads();

    const float* W2 = w2 + (size_t)e * DM * FF + (size_t)n0 * FF;
    const float* Ain = g_inter + (size_t)(base + m0) * FF;
    int mlim = cnt - m0;

    float acc[4][4][4];
    #pragma unroll
    for (int i = 0; i < 4; i++)
        #pragma unroll
        for (int j = 0; j < 4; j++)
            #pragma unroll
            for (int c = 0; c < 4; c++) acc[i][j][c] = 0.f;

    float4 ra[4], rb[2];
    auto ldg_chunk = [&](int k0) {
        #pragma unroll
        for (int p = 0; p < 4; p++) {               // A: 2048 f4 / 512 thr
            int f = tid + p * 512;
            int row = f >> 3, j = f & 7;
            ra[p] = make_float4(0.f, 0.f, 0.f, 0.f);
            if (row < mlim) ra[p] = *(const float4*)(Ain + (size_t)row * FF + k0 + j * 4);
        }
        #pragma unroll
        for (int p = 0; p < 2; p++) {               // B: 1024 f4 / 512 thr
            int f = tid + p * 512;
            int row = f >> 3, j = f & 7;
            rb[p] = *(const float4*)(W2 + (size_t)row * FF + k0 + j * 4);
        }
    };
    auto sts_chunk = [&](int buf) {
        uint32_t* A = Abuf + buf * TILE256_U32;
        uint32_t* B = Bbuf + buf * TILE128_U32;
        #pragma unroll
        for (int p = 0; p < 4; p++) {
            int f = tid + p * 512;
            int row = f >> 3, j = f & 7;
            *(uint4*)(A + row * PAD + j * 4) = to_tf32_v4(ra[p]);
        }
        #pragma unroll
        for (int p = 0; p < 2; p++) {
            int f = tid + p * 512;
            int row = f >> 3, j = f & 7;
            *(uint4*)(B + row * PAD + j * 4) = to_tf32_v4(rb[p]);
        }
    };
    auto compute_chunk = [&](int buf) {
        uint32_t Ab = sbA + buf * TILE256_U32 * 4;
        uint32_t Bb = sbB + buf * TILE128_U32 * 4;
        #pragma unroll
        for (int ks = 0; ks < 4; ks++) {
            uint32_t afr[4][4];
            #pragma unroll
            for (int mt = 0; mt < 4; mt++) {
                int arow = warpM * 64 + mt * 16 + (grp & 1) * 8 + rowi;
                uint32_t addr = Ab + (uint32_t)(arow * PAD + ks * 8 + (grp >> 1) * 4) * 4;
                ldsm_x4(addr, afr[mt]);
            }
            uint32_t bf[2][4];
            #pragma unroll
            for (int np = 0; np < 2; np++) {
                int nrow = warpN * 32 + np * 16 + (grp >> 1) * 8 + rowi;
                uint32_t off = (uint32_t)(nrow * PAD + ks * 8 + (grp & 1) * 4) * 4;
                ldsm_x4(Bb + off, bf[np]);
            }
            #pragma unroll
            for (int np = 0; np < 2; np++) {
                #pragma unroll
                for (int sub = 0; sub < 2; sub++) {
                    int nt = np * 2 + sub;
                    #pragma unroll
                    for (int mt = 0; mt < 4; mt++)
                        mma_tf32(acc[mt][nt], afr[mt], &bf[np][sub * 2]);
                }
            }
        }
    };

    const int NIT = FF / KC;   // 128
    ldg_chunk(0);
    sts_chunk(0);
    __syncthreads();
    for (int it = 0; it < NIT; ++it) {
        if (it + 1 < NIT) ldg_chunk((it + 1) * KC);
        compute_chunk(it & 1);
        if (it + 1 < NIT) sts_chunk((it + 1) & 1);
        __syncthreads();
    }

    // epilogue: weighted deterministic scatter-add (2 contributions per element)
    #pragma unroll
    for (int mt = 0; mt < 4; mt++) {
        #pragma unroll
        for (int half = 0; half < 2; half++) {
            int rl = warpM * 64 + mt * 16 + half * 8 + g;
            int t = toks[rl];
            if (t >= 0) {
                float w = wgts[rl];
                float* orow = out + (size_t)t * DM + n0;
                #pragma unroll
                for (int nt = 0; nt < 4; nt++) {
                    int col = warpN * 32 + nt * 8 + 2 * tq;
                    atomicAdd(orow + col,     w * acc[mt][nt][half * 2 + 0]);
                    atomicAdd(orow + col + 1, w * acc[mt][nt][half * 2 + 1]);
                }
            }
        }
    }
}

// ---------------- launch ----------------
extern "C" void kernel_launch(void* const* d_in, const int* in_sizes, int n_in,
                              void* d_out, int out_size) {
    const float* x  = (const float*)d_in[0];   // [T, DM]
    const float* gw = (const float*)d_in[1];   // [NE, DM]
    const float* w1 = (const float*)d_in[2];   // [NE, FF, DM]
    const float* w3 = (const float*)d_in[3];   // [NE, FF, DM]
    const float* w2 = (const float*)d_in[4];   // [NE, DM, FF]

    float* out    = (float*)d_out;             // [T, DM] then router_logits [T, NE]
    float* logits = out + (size_t)T * DM;

    cudaFuncSetAttribute(gemm1_tc, cudaFuncAttributeMaxDynamicSharedMemorySize, G1_SMEM_BYTES);
    cudaFuncSetAttribute(gemm2_tc, cudaFuncAttributeMaxDynamicSharedMemorySize, G2_SMEM_BYTES);

    cudaMemsetAsync(d_out, 0, (size_t)T * DM * sizeof(float));
    init_kernel<<<1, 32>>>();
    router_kernel<<<T, 256>>>(x, gw, logits);
    assign_kernel<<<1, 256>>>();
    gemm1_tc<<<dim3(FF / 128, (2 * T) / 128, NE), 512, G1_SMEM_BYTES>>>(x, w1, w3);
    gemm2_tc<<<dim3(DM / 128, (2 * T) / 256, NE), 512, G2_SMEM_BYTES>>>(w2, out);
}